// round 6
// baseline (speedup 1.0000x reference)
#include <cuda_runtime.h>
#include <cuda_fp16.h>
#include <math.h>

#define NN   50000
#define C0   128      // HEADS*HID
#define OUTC 64
#define EMAX 800000
#define NEG  0.2f

// ---------------- scratch (static device globals; no allocation) ------------
__device__ __align__(16) int    g_deg[NN];
__device__ __align__(16) int    g_off[NN + 4];
__device__ __align__(16) int    g_cur[NN];
__device__ __align__(16) int    g_csr[EMAX];
__device__ __align__(16) __half g_h0h[(size_t)NN * C0];
__device__ __align__(16) __half g_h1h[(size_t)NN * OUTC];
__device__ __align__(16) float  g_as0[NN * 2];
__device__ __align__(16) float  g_ad0[NN * 2];
__device__ __align__(16) float  g_agg0[(size_t)NN * C0];
__device__ __align__(16) float  g_bnsum[C0];
__device__ __align__(16) float  g_bnsq[C0];
__device__ __align__(16) float  g_a1s[NN];
__device__ __align__(16) float  g_a1d[NN];

// ---------------- CSR build -------------------------------------------------
__global__ void k_zero() {
    int i = blockIdx.x * blockDim.x + threadIdx.x;
    if (i < NN) g_deg[i] = 0;
    if (i < C0) { g_bnsum[i] = 0.f; g_bnsq[i] = 0.f; }
}

__global__ void k_count(const int* __restrict__ ei, int E) {
    int i0 = (blockIdx.x * blockDim.x + threadIdx.x) * 4;
#pragma unroll
    for (int j = 0; j < 4; j++) {
        int i = i0 + j;
        if (i < E) {
            int d = ei[E + i];
            if (d >= 0 && d < NN) atomicAdd(&g_deg[d], 1);
        }
    }
}

__global__ void k_scan() {
    __shared__ int part[1024];
    int t = threadIdx.x;
    const int chunk = (NN + 1023) / 1024;
    int beg = t * chunk;
    int end = min(beg + chunk, NN);
    int s = 0;
    for (int i = beg; i < end; i++) s += g_deg[i];
    part[t] = s;
    __syncthreads();
    for (int d = 1; d < 1024; d <<= 1) {
        int v = 0;
        if (t >= d) v = part[t - d];
        __syncthreads();
        part[t] += v;
        __syncthreads();
    }
    int base = (t == 0) ? 0 : part[t - 1];
    for (int i = beg; i < end; i++) {
        g_off[i] = base; g_cur[i] = base; base += g_deg[i];
    }
    if (t == 1023) g_off[NN] = part[1023];
}

__global__ void k_scatter(const int* __restrict__ ei, int E) {
    int i0 = (blockIdx.x * blockDim.x + threadIdx.x) * 4;
#pragma unroll
    for (int j = 0; j < 4; j++) {
        int i = i0 + j;
        if (i < E) {
            int d = ei[E + i];
            int s = ei[i];
            if (d >= 0 && d < NN && s >= 0 && s < NN) {
                int p = atomicAdd(&g_cur[d], 1);
                g_csr[p] = s;
            }
        }
    }
}

// ---------------- tf32 helpers ----------------------------------------------
__device__ __forceinline__ unsigned f2tf(float x) {
    unsigned u;
    asm("cvt.rna.tf32.f32 %0, %1;" : "=r"(u) : "f"(x));
    return u;
}

__device__ __forceinline__ void mma_tf32(float* c, const unsigned* a, const unsigned* b) {
    asm volatile(
        "mma.sync.aligned.m16n8k8.row.col.f32.tf32.tf32.f32 "
        "{%0,%1,%2,%3}, {%4,%5,%6,%7}, {%8,%9}, {%0,%1,%2,%3};"
        : "+f"(c[0]), "+f"(c[1]), "+f"(c[2]), "+f"(c[3])
        : "r"(a[0]), "r"(a[1]), "r"(a[2]), "r"(a[3]), "r"(b[0]), "r"(b[1]));
}

// ---------------- tensor-core GEMM (K=128) + fused epilogue ------------------
// Warp tile 64x64, 3-term tf32 split (fp32-grade accuracy).
// BMW x BNW warps; BM = BMW*64 rows, BN = BNW*64 cols. 128 threads.
// TRANS (layer1): A = g_agg0 with fused BatchNorm+ELU; h -> g_h1h, logits -> g_a1s/d.
// else  (layer0): A = data;                             h -> g_h0h, logits -> g_as0/ad0.
template <int BMW, int BNW, bool TRANS>
__global__ __launch_bounds__(128) void k_gemm_tc(const float* __restrict__ Ax,
                                                 const float* __restrict__ W,
                                                 const float* __restrict__ att_s,
                                                 const float* __restrict__ att_d,
                                                 const float* __restrict__ gamma,
                                                 const float* __restrict__ beta,
                                                 int nrows) {
    const int BM = BMW * 64, BN = BNW * 64;
    __shared__ unsigned As_hi[BM][12], As_lo[BM][12];
    __shared__ unsigned Bs_hi[8][BN + 8], Bs_lo[8][BN + 8];
    __shared__ float sSc[128], sSh[128];

    const float* A = TRANS ? g_agg0 : Ax;
    __half* hptr = TRANS ? g_h1h : g_h0h;

    int tid = threadIdx.x;
    int warp = tid >> 5, lane = tid & 31;
    int g = lane >> 2, tig = lane & 3;
    int mwarp = warp % BMW, nwarp = warp / BMW;
    int row0 = blockIdx.x * BM;

    if (TRANS) {
        if (tid < 128) {
            float mu = g_bnsum[tid] / (float)NN;
            float var = g_bnsq[tid] / (float)NN - mu * mu;
            float sc = gamma[tid] * rsqrtf(var + 1e-5f);
            sSc[tid] = sc;
            sSh[tid] = beta[tid] - mu * sc;
        }
        __syncthreads();
    }

    float acc[4][8][4];
#pragma unroll
    for (int f = 0; f < 4; f++)
#pragma unroll
        for (int j = 0; j < 8; j++)
#pragma unroll
            for (int q = 0; q < 4; q++) acc[f][j][q] = 0.f;

    for (int kk = 0; kk < 128; kk += 8) {
        // ---- A tile -> smem (hi/lo) ----
        for (int rr = tid; rr < BM; rr += 128) {
            int grow = row0 + rr;
            float x[8];
            if (grow < nrows) {
                float4 v0 = *(const float4*)&A[(size_t)grow * 128 + kk];
                float4 v1 = *(const float4*)&A[(size_t)grow * 128 + kk + 4];
                x[0] = v0.x; x[1] = v0.y; x[2] = v0.z; x[3] = v0.w;
                x[4] = v1.x; x[5] = v1.y; x[6] = v1.z; x[7] = v1.w;
            } else {
#pragma unroll
                for (int k = 0; k < 8; k++) x[k] = 0.f;
            }
            if (TRANS) {
#pragma unroll
                for (int k = 0; k < 8; k++) {
                    int c = kk + k;
                    float t = x[k] * sSc[c] + sSh[c];
                    x[k] = t > 0.f ? t : expm1f(t);
                }
            }
#pragma unroll
            for (int k = 0; k < 8; k++) {
                unsigned hi = f2tf(x[k]);
                As_hi[rr][k] = hi;
                As_lo[rr][k] = f2tf(x[k] - __uint_as_float(hi));
            }
        }
        // ---- B tile -> smem (hi/lo) ----
        {
            const int EPT = BN / 16;             // 8 (BN=128) or 4 (BN=64)
            int br = tid >> 4, bc = (tid & 15) * EPT;
#pragma unroll
            for (int j = 0; j < EPT; j += 4) {
                float4 v = *(const float4*)&W[(size_t)(kk + br) * BN + bc + j];
                float y[4] = {v.x, v.y, v.z, v.w};
#pragma unroll
                for (int q = 0; q < 4; q++) {
                    unsigned hi = f2tf(y[q]);
                    Bs_hi[br][bc + j + q] = hi;
                    Bs_lo[br][bc + j + q] = f2tf(y[q] - __uint_as_float(hi));
                }
            }
        }
        __syncthreads();

        // ---- fragments + MMA ----
        unsigned bh[8][2], bl[8][2];
#pragma unroll
        for (int j = 0; j < 8; j++) {
            int n = nwarp * 64 + j * 8 + g;
            bh[j][0] = Bs_hi[tig][n];     bh[j][1] = Bs_hi[tig + 4][n];
            bl[j][0] = Bs_lo[tig][n];     bl[j][1] = Bs_lo[tig + 4][n];
        }
#pragma unroll
        for (int f = 0; f < 4; f++) {
            int r0 = mwarp * 64 + f * 16 + g;
            unsigned ah[4], al[4];
            ah[0] = As_hi[r0][tig];     ah[1] = As_hi[r0 + 8][tig];
            ah[2] = As_hi[r0][tig + 4]; ah[3] = As_hi[r0 + 8][tig + 4];
            al[0] = As_lo[r0][tig];     al[1] = As_lo[r0 + 8][tig];
            al[2] = As_lo[r0][tig + 4]; al[3] = As_lo[r0 + 8][tig + 4];
#pragma unroll
            for (int j = 0; j < 8; j++) {
                mma_tf32(acc[f][j], ah, bh[j]);
                mma_tf32(acc[f][j], al, bh[j]);
                mma_tf32(acc[f][j], ah, bl[j]);
            }
        }
        __syncthreads();
    }

    // ---- epilogue: fp16 feature store + fused attention logits ----
#pragma unroll
    for (int f = 0; f < 4; f++) {
        int rr0 = row0 + mwarp * 64 + f * 16 + g;
        int rr1 = rr0 + 8;
        float ps0 = 0.f, pd0 = 0.f, ps1 = 0.f, pd1 = 0.f;
#pragma unroll
        for (int j = 0; j < 8; j++) {
            int n0 = nwarp * 64 + j * 8 + tig * 2;
            float c0 = acc[f][j][0], c1 = acc[f][j][1];
            float c2 = acc[f][j][2], c3 = acc[f][j][3];
            float s0 = att_s[n0], s1 = att_s[n0 + 1];
            float d0 = att_d[n0], d1 = att_d[n0 + 1];
            ps0 += c0 * s0 + c1 * s1; pd0 += c0 * d0 + c1 * d1;
            ps1 += c2 * s0 + c3 * s1; pd1 += c2 * d0 + c3 * d1;
            if (rr0 < nrows)
                *reinterpret_cast<__half2*>(&hptr[(size_t)rr0 * BN + n0]) = __floats2half2_rn(c0, c1);
            if (rr1 < nrows)
                *reinterpret_cast<__half2*>(&hptr[(size_t)rr1 * BN + n0]) = __floats2half2_rn(c2, c3);
        }
#pragma unroll
        for (int o = 1; o < 4; o <<= 1) {
            ps0 += __shfl_xor_sync(0xffffffffu, ps0, o);
            pd0 += __shfl_xor_sync(0xffffffffu, pd0, o);
            ps1 += __shfl_xor_sync(0xffffffffu, ps1, o);
            pd1 += __shfl_xor_sync(0xffffffffu, pd1, o);
        }
        if (tig == 0) {
            if (TRANS) {
                if (rr0 < nrows) { g_a1s[rr0] = ps0; g_a1d[rr0] = pd0; }
                if (rr1 < nrows) { g_a1s[rr1] = ps1; g_a1d[rr1] = pd1; }
            } else {
                if (rr0 < nrows) { g_as0[rr0 * 2 + nwarp] = ps0; g_ad0[rr0 * 2 + nwarp] = pd0; }
                if (rr1 < nrows) { g_as0[rr1 * 2 + nwarp] = ps1; g_ad0[rr1 * 2 + nwarp] = pd1; }
            }
        }
    }
}

// ---------------- single-pass softmax-aggregate (warp per node) -------------
__device__ __forceinline__ float lrelu(float x) { return x > 0.f ? x : NEG * x; }

__global__ __launch_bounds__(256) void k_agg0(const float* __restrict__ bias0) {
    __shared__ float s_sum[C0];
    __shared__ float s_sq[C0];
    int tid = threadIdx.x;
    if (tid < C0) { s_sum[tid] = 0.f; s_sq[tid] = 0.f; }
    __syncthreads();

    int n = (blockIdx.x * blockDim.x + tid) >> 5;
    int lane = tid & 31;
    if (n < NN) {
        int beg = g_off[n], end = g_off[n + 1];
        float2 ad = *(const float2*)&g_ad0[n * 2];
        float2 an = *(const float2*)&g_as0[n * 2];
        bool head1 = lane >= 16;
        float adh = head1 ? ad.y : ad.x;
        float anh = head1 ? an.y : an.x;
        int coff = lane * 4;

        float d = 0.f;
        float4 acc = make_float4(0.f, 0.f, 0.f, 0.f);
#pragma unroll 2
        for (int i = beg; i < end; i++) {
            int s = g_csr[i];
            float2 a = *(const float2*)&g_as0[s * 2];
            float w = __expf(lrelu((head1 ? a.y : a.x) + adh));
            d += w;
            uint2 u = *(const uint2*)&g_h0h[(size_t)s * 128 + coff];
            float2 p0 = __half22float2(*(__half2*)&u.x);
            float2 p1 = __half22float2(*(__half2*)&u.y);
            acc.x = fmaf(p0.x, w, acc.x); acc.y = fmaf(p0.y, w, acc.y);
            acc.z = fmaf(p1.x, w, acc.z); acc.w = fmaf(p1.y, w, acc.w);
        }
        { // self loop
            float w = __expf(lrelu(anh + adh));
            d += w;
            uint2 u = *(const uint2*)&g_h0h[(size_t)n * 128 + coff];
            float2 p0 = __half22float2(*(__half2*)&u.x);
            float2 p1 = __half22float2(*(__half2*)&u.y);
            acc.x = fmaf(p0.x, w, acc.x); acc.y = fmaf(p0.y, w, acc.y);
            acc.z = fmaf(p1.x, w, acc.z); acc.w = fmaf(p1.y, w, acc.w);
        }
        float inv = 1.f / (d + 1e-16f);
        float4 b = *(const float4*)&bias0[coff];
        float4 o;
        o.x = acc.x * inv + b.x; o.y = acc.y * inv + b.y;
        o.z = acc.z * inv + b.z; o.w = acc.w * inv + b.w;
        *(float4*)&g_agg0[(size_t)n * 128 + coff] = o;

        atomicAdd(&s_sum[coff + 0], o.x); atomicAdd(&s_sq[coff + 0], o.x * o.x);
        atomicAdd(&s_sum[coff + 1], o.y); atomicAdd(&s_sq[coff + 1], o.y * o.y);
        atomicAdd(&s_sum[coff + 2], o.z); atomicAdd(&s_sq[coff + 2], o.z * o.z);
        atomicAdd(&s_sum[coff + 3], o.w); atomicAdd(&s_sq[coff + 3], o.w * o.w);
    }
    __syncthreads();
    if (tid < C0) {
        atomicAdd(&g_bnsum[tid], s_sum[tid]);
        atomicAdd(&g_bnsq[tid], s_sq[tid]);
    }
}

__global__ __launch_bounds__(256) void k_agg1(const float* __restrict__ bias1,
                                              float* __restrict__ out) {
    int n = (blockIdx.x * blockDim.x + threadIdx.x) >> 5;
    int lane = threadIdx.x & 31;
    if (n >= NN) return;
    int beg = g_off[n], end = g_off[n + 1];
    float ad = g_a1d[n];
    float an = g_a1s[n];
    int coff = lane * 2;

    float d = 0.f;
    float2 acc = make_float2(0.f, 0.f);
#pragma unroll 2
    for (int i = beg; i < end; i++) {
        int s = g_csr[i];
        float w = __expf(lrelu(g_a1s[s] + ad));
        d += w;
        unsigned u = *(const unsigned*)&g_h1h[(size_t)s * 64 + coff];
        float2 p = __half22float2(*(__half2*)&u);
        acc.x = fmaf(p.x, w, acc.x);
        acc.y = fmaf(p.y, w, acc.y);
    }
    { // self loop
        float w = __expf(lrelu(an + ad));
        d += w;
        unsigned u = *(const unsigned*)&g_h1h[(size_t)n * 64 + coff];
        float2 p = __half22float2(*(__half2*)&u);
        acc.x = fmaf(p.x, w, acc.x);
        acc.y = fmaf(p.y, w, acc.y);
    }
    float inv = 1.f / (d + 1e-16f);
    float2 b = *(const float2*)&bias1[coff];
    float2 r = make_float2(acc.x * inv + b.x, acc.y * inv + b.y);
    *(float2*)&out[(size_t)n * 64 + coff] = r;
}

// ---------------- launch ----------------------------------------------------
extern "C" void kernel_launch(void* const* d_in, const int* in_sizes, int n_in,
                              void* d_out, int out_size) {
    const float* data = (const float*)d_in[0];
    const int*   ei   = (const int*)d_in[1];    // int32 (JAX x64 disabled)
    const float* W0   = (const float*)d_in[2];
    const float* as0  = (const float*)d_in[3];
    const float* ad0  = (const float*)d_in[4];
    const float* b0   = (const float*)d_in[5];
    const float* g0   = (const float*)d_in[6];
    const float* be0  = (const float*)d_in[7];
    const float* W1   = (const float*)d_in[8];
    const float* as1  = (const float*)d_in[9];
    const float* ad1  = (const float*)d_in[10];
    const float* b1   = (const float*)d_in[11];
    float* out = (float*)d_out;

    int E = in_sizes[1] / 2;
    if (E > EMAX) E = EMAX;

    int warpBlocks = (NN * 32 + 255) / 256;
    int e4Blocks = (E + 1023) / 1024;       // 4 edges/thread, 256 threads

    static cudaStream_t s2 = nullptr;
    static cudaEvent_t evFork = nullptr, evJoin = nullptr;
    if (!s2) {
        cudaStreamCreateWithFlags(&s2, cudaStreamNonBlocking);
        cudaEventCreateWithFlags(&evFork, cudaEventDisableTiming);
        cudaEventCreateWithFlags(&evJoin, cudaEventDisableTiming);
    }

    // fork: CSR chain on s2
    cudaEventRecord(evFork, 0);
    cudaStreamWaitEvent(s2, evFork, 0);
    k_zero<<<(NN + 255) / 256, 256, 0, s2>>>();
    k_count<<<e4Blocks, 256, 0, s2>>>(ei, E);
    k_scan<<<1, 1024, 0, s2>>>();
    k_scatter<<<e4Blocks, 256, 0, s2>>>(ei, E);
    cudaEventRecord(evJoin, s2);

    // main stream: GEMM0 (tensor cores) — independent of CSR
    k_gemm_tc<2, 2, false><<<(NN + 127) / 128, 128>>>(data, W0, as0, ad0, nullptr, nullptr, NN);

    // join, then dependent chain
    cudaStreamWaitEvent(0, evJoin, 0);
    k_agg0<<<warpBlocks, 256>>>(b0);
    k_gemm_tc<4, 1, true><<<(NN + 255) / 256, 128>>>(nullptr, W1, as1, ad1, g0, be0, NN);
    k_agg1<<<warpBlocks, 256>>>(b1, out);
}

// round 7
// speedup vs baseline: 1.0493x; 1.0493x over previous
#include <cuda_runtime.h>
#include <cuda_fp16.h>
#include <math.h>

#define NN   50000
#define C0   128      // HEADS*HID
#define OUTC 64
#define EMAX 800000
#define NEG  0.2f

// ---------------- scratch (static device globals; no allocation) ------------
__device__ __align__(16) int    g_deg[NN];
__device__ __align__(16) int    g_off[NN + 4];
__device__ __align__(16) int    g_cur[NN];
__device__ __align__(16) int    g_csr[EMAX];
__device__ __align__(16) __half g_h0h[(size_t)NN * C0];
__device__ __align__(16) __half g_h1h[(size_t)NN * OUTC];
__device__ __align__(16) float  g_as0[NN * 2];
__device__ __align__(16) float  g_ad0[NN * 2];
__device__ __align__(16) float  g_agg0[(size_t)NN * C0];
__device__ __align__(16) float  g_bnsum[C0];
__device__ __align__(16) float  g_bnsq[C0];
__device__ __align__(16) float  g_a1s[NN];
__device__ __align__(16) float  g_a1d[NN];

// ---------------- CSR build -------------------------------------------------
__global__ void k_zero() {
    int i = blockIdx.x * blockDim.x + threadIdx.x;
    if (i < NN) g_deg[i] = 0;
    if (i < C0) { g_bnsum[i] = 0.f; g_bnsq[i] = 0.f; }
}

__global__ void k_count(const int* __restrict__ ei, int E) {
    int i = blockIdx.x * blockDim.x + threadIdx.x;
    if (i < E) {
        int d = ei[E + i];
        if (d >= 0 && d < NN) atomicAdd(&g_deg[d], 1);
    }
}

__global__ void k_scan() {
    __shared__ int part[1024];
    int t = threadIdx.x;
    const int chunk = (NN + 1023) / 1024;
    int beg = t * chunk;
    int end = min(beg + chunk, NN);
    int s = 0;
    for (int i = beg; i < end; i++) s += g_deg[i];
    part[t] = s;
    __syncthreads();
    for (int d = 1; d < 1024; d <<= 1) {
        int v = 0;
        if (t >= d) v = part[t - d];
        __syncthreads();
        part[t] += v;
        __syncthreads();
    }
    int base = (t == 0) ? 0 : part[t - 1];
    for (int i = beg; i < end; i++) {
        g_off[i] = base; g_cur[i] = base; base += g_deg[i];
    }
    if (t == 1023) g_off[NN] = part[1023];
}

__global__ void k_scatter(const int* __restrict__ ei, int E) {
    int i = blockIdx.x * blockDim.x + threadIdx.x;
    if (i < E) {
        int d = ei[E + i];
        int s = ei[i];
        if (d >= 0 && d < NN && s >= 0 && s < NN) {
            int p = atomicAdd(&g_cur[d], 1);
            g_csr[p] = s;
        }
    }
}

// ---------------- tf32 helpers ----------------------------------------------
__device__ __forceinline__ unsigned f2tf(float x) {
    unsigned u;
    asm("cvt.rna.tf32.f32 %0, %1;" : "=r"(u) : "f"(x));
    return u;
}

__device__ __forceinline__ void mma_tf32(float* c, const unsigned* a, const unsigned* b) {
    asm volatile(
        "mma.sync.aligned.m16n8k8.row.col.f32.tf32.tf32.f32 "
        "{%0,%1,%2,%3}, {%4,%5,%6,%7}, {%8,%9}, {%0,%1,%2,%3};"
        : "+f"(c[0]), "+f"(c[1]), "+f"(c[2]), "+f"(c[3])
        : "r"(a[0]), "r"(a[1]), "r"(a[2]), "r"(a[3]), "r"(b[0]), "r"(b[1]));
}

// ---------------- tensor-core GEMM (K=128) + fused epilogue ------------------
// 256 threads = 8 warps, warp tile 32x64 (acc = 64 regs), 3-term tf32 split.
// MW x NW warp grid, MW*NW == 8. BM = MW*32 rows, BN = NW*64 cols.
// Layer0: MW=4,NW=2 -> 128x128 (n-warp == head). Layer1: MW=8,NW=1 -> 256x64.
// TRANS (layer1): A = g_agg0 with fused BatchNorm+ELU; h->g_h1h, logits->g_a1s/d.
template <int MW, int NW, bool TRANS>
__global__ __launch_bounds__(256) void k_gemm_tc(const float* __restrict__ Ax,
                                                 const float* __restrict__ W,
                                                 const float* __restrict__ att_s,
                                                 const float* __restrict__ att_d,
                                                 const float* __restrict__ gamma,
                                                 const float* __restrict__ beta,
                                                 int nrows) {
    const int BM = MW * 32, BN = NW * 64;
    __shared__ unsigned As_hi[BM][12], As_lo[BM][12];
    __shared__ unsigned Bs_hi[8][BN + 8], Bs_lo[8][BN + 8];
    __shared__ float sSc[128], sSh[128];

    const float* A = TRANS ? g_agg0 : Ax;
    __half* hptr = TRANS ? g_h1h : g_h0h;

    int tid = threadIdx.x;
    int warp = tid >> 5, lane = tid & 31;
    int g = lane >> 2, tig = lane & 3;
    int mwarp = warp % MW, nwarp = warp / MW;
    int row0 = blockIdx.x * BM;

    if (TRANS) {
        if (tid < 128) {
            float mu = g_bnsum[tid] / (float)NN;
            float var = g_bnsq[tid] / (float)NN - mu * mu;
            float sc = gamma[tid] * rsqrtf(var + 1e-5f);
            sSc[tid] = sc;
            sSh[tid] = beta[tid] - mu * sc;
        }
        __syncthreads();
    }

    float acc[2][8][4];
#pragma unroll
    for (int f = 0; f < 2; f++)
#pragma unroll
        for (int j = 0; j < 8; j++)
#pragma unroll
            for (int q = 0; q < 4; q++) acc[f][j][q] = 0.f;

    for (int kk = 0; kk < 128; kk += 8) {
        // ---- A tile -> smem (hi/lo) ----
        if (BM == 128) {          // 2 threads per row, 4 floats each
            int rr = tid >> 1;
            int ko = (tid & 1) * 4;
            int grow = row0 + rr;
            float4 v = make_float4(0.f, 0.f, 0.f, 0.f);
            if (grow < nrows) v = *(const float4*)&A[(size_t)grow * 128 + kk + ko];
            float x[4] = {v.x, v.y, v.z, v.w};
            if (TRANS) {
#pragma unroll
                for (int k = 0; k < 4; k++) {
                    int c = kk + ko + k;
                    float t = x[k] * sSc[c] + sSh[c];
                    x[k] = t > 0.f ? t : expm1f(t);
                }
            }
#pragma unroll
            for (int k = 0; k < 4; k++) {
                unsigned hi = f2tf(x[k]);
                As_hi[rr][ko + k] = hi;
                As_lo[rr][ko + k] = f2tf(x[k] - __uint_as_float(hi));
            }
        } else {                  // 1 thread per row, 8 floats
            int rr = tid;
            int grow = row0 + rr;
            float x[8];
            if (grow < nrows) {
                float4 v0 = *(const float4*)&A[(size_t)grow * 128 + kk];
                float4 v1 = *(const float4*)&A[(size_t)grow * 128 + kk + 4];
                x[0] = v0.x; x[1] = v0.y; x[2] = v0.z; x[3] = v0.w;
                x[4] = v1.x; x[5] = v1.y; x[6] = v1.z; x[7] = v1.w;
            } else {
#pragma unroll
                for (int k = 0; k < 8; k++) x[k] = 0.f;
            }
            if (TRANS) {
#pragma unroll
                for (int k = 0; k < 8; k++) {
                    int c = kk + k;
                    float t = x[k] * sSc[c] + sSh[c];
                    x[k] = t > 0.f ? t : expm1f(t);
                }
            }
#pragma unroll
            for (int k = 0; k < 8; k++) {
                unsigned hi = f2tf(x[k]);
                As_hi[rr][k] = hi;
                As_lo[rr][k] = f2tf(x[k] - __uint_as_float(hi));
            }
        }
        // ---- B tile -> smem (hi/lo) ----
        if (BN == 128) {
            int br = tid >> 5, bc = (tid & 31) * 4;
            float4 v = *(const float4*)&W[(size_t)(kk + br) * BN + bc];
            float y[4] = {v.x, v.y, v.z, v.w};
#pragma unroll
            for (int q = 0; q < 4; q++) {
                unsigned hi = f2tf(y[q]);
                Bs_hi[br][bc + q] = hi;
                Bs_lo[br][bc + q] = f2tf(y[q] - __uint_as_float(hi));
            }
        } else {
            int br = tid >> 5, bc = (tid & 31) * 2;
            float2 v = *(const float2*)&W[(size_t)(kk + br) * BN + bc];
            float y[2] = {v.x, v.y};
#pragma unroll
            for (int q = 0; q < 2; q++) {
                unsigned hi = f2tf(y[q]);
                Bs_hi[br][bc + q] = hi;
                Bs_lo[br][bc + q] = f2tf(y[q] - __uint_as_float(hi));
            }
        }
        __syncthreads();

        // ---- fragments + MMA ----
        unsigned bh[8][2], bl[8][2];
#pragma unroll
        for (int j = 0; j < 8; j++) {
            int n = nwarp * 64 + j * 8 + g;
            bh[j][0] = Bs_hi[tig][n];     bh[j][1] = Bs_hi[tig + 4][n];
            bl[j][0] = Bs_lo[tig][n];     bl[j][1] = Bs_lo[tig + 4][n];
        }
#pragma unroll
        for (int f = 0; f < 2; f++) {
            int r0 = mwarp * 32 + f * 16 + g;
            unsigned ah[4], al[4];
            ah[0] = As_hi[r0][tig];     ah[1] = As_hi[r0 + 8][tig];
            ah[2] = As_hi[r0][tig + 4]; ah[3] = As_hi[r0 + 8][tig + 4];
            al[0] = As_lo[r0][tig];     al[1] = As_lo[r0 + 8][tig];
            al[2] = As_lo[r0][tig + 4]; al[3] = As_lo[r0 + 8][tig + 4];
#pragma unroll
            for (int j = 0; j < 8; j++) {
                mma_tf32(acc[f][j], ah, bh[j]);
                mma_tf32(acc[f][j], al, bh[j]);
                mma_tf32(acc[f][j], ah, bl[j]);
            }
        }
        __syncthreads();
    }

    // ---- epilogue: fp16 feature store + fused attention logits ----
#pragma unroll
    for (int f = 0; f < 2; f++) {
        int rr0 = row0 + mwarp * 32 + f * 16 + g;
        int rr1 = rr0 + 8;
        float ps0 = 0.f, pd0 = 0.f, ps1 = 0.f, pd1 = 0.f;
#pragma unroll
        for (int j = 0; j < 8; j++) {
            int n0 = nwarp * 64 + j * 8 + tig * 2;
            float c0 = acc[f][j][0], c1 = acc[f][j][1];
            float c2 = acc[f][j][2], c3 = acc[f][j][3];
            float s0 = att_s[n0], s1 = att_s[n0 + 1];
            float d0 = att_d[n0], d1 = att_d[n0 + 1];
            ps0 += c0 * s0 + c1 * s1; pd0 += c0 * d0 + c1 * d1;
            ps1 += c2 * s0 + c3 * s1; pd1 += c2 * d0 + c3 * d1;
            if (rr0 < nrows)
                *reinterpret_cast<__half2*>(&hptr[(size_t)rr0 * BN + n0]) = __floats2half2_rn(c0, c1);
            if (rr1 < nrows)
                *reinterpret_cast<__half2*>(&hptr[(size_t)rr1 * BN + n0]) = __floats2half2_rn(c2, c3);
        }
#pragma unroll
        for (int o = 1; o < 4; o <<= 1) {
            ps0 += __shfl_xor_sync(0xffffffffu, ps0, o);
            pd0 += __shfl_xor_sync(0xffffffffu, pd0, o);
            ps1 += __shfl_xor_sync(0xffffffffu, ps1, o);
            pd1 += __shfl_xor_sync(0xffffffffu, pd1, o);
        }
        if (tig == 0) {
            if (TRANS) {
                if (rr0 < nrows) { g_a1s[rr0] = ps0; g_a1d[rr0] = pd0; }
                if (rr1 < nrows) { g_a1s[rr1] = ps1; g_a1d[rr1] = pd1; }
            } else {
                if (rr0 < nrows) { g_as0[rr0 * 2 + nwarp] = ps0; g_ad0[rr0 * 2 + nwarp] = pd0; }
                if (rr1 < nrows) { g_as0[rr1 * 2 + nwarp] = ps1; g_ad0[rr1 * 2 + nwarp] = pd1; }
            }
        }
    }
}

// ---------------- single-pass softmax-aggregate (warp per node) -------------
__device__ __forceinline__ float lrelu(float x) { return x > 0.f ? x : NEG * x; }

__global__ __launch_bounds__(256) void k_agg0(const float* __restrict__ bias0) {
    __shared__ float s_sum[C0];
    __shared__ float s_sq[C0];
    int tid = threadIdx.x;
    if (tid < C0) { s_sum[tid] = 0.f; s_sq[tid] = 0.f; }
    __syncthreads();

    int n = (blockIdx.x * blockDim.x + tid) >> 5;
    int lane = tid & 31;
    if (n < NN) {
        int beg = g_off[n], end = g_off[n + 1];
        float2 ad = *(const float2*)&g_ad0[n * 2];
        float2 an = *(const float2*)&g_as0[n * 2];
        bool head1 = lane >= 16;
        float adh = head1 ? ad.y : ad.x;
        float anh = head1 ? an.y : an.x;
        int coff = lane * 4;

        float d = 0.f;
        float4 acc = make_float4(0.f, 0.f, 0.f, 0.f);
#pragma unroll 2
        for (int i = beg; i < end; i++) {
            int s = g_csr[i];
            float2 a = *(const float2*)&g_as0[s * 2];
            float w = __expf(lrelu((head1 ? a.y : a.x) + adh));
            d += w;
            uint2 u = *(const uint2*)&g_h0h[(size_t)s * 128 + coff];
            float2 p0 = __half22float2(*(__half2*)&u.x);
            float2 p1 = __half22float2(*(__half2*)&u.y);
            acc.x = fmaf(p0.x, w, acc.x); acc.y = fmaf(p0.y, w, acc.y);
            acc.z = fmaf(p1.x, w, acc.z); acc.w = fmaf(p1.y, w, acc.w);
        }
        { // self loop
            float w = __expf(lrelu(anh + adh));
            d += w;
            uint2 u = *(const uint2*)&g_h0h[(size_t)n * 128 + coff];
            float2 p0 = __half22float2(*(__half2*)&u.x);
            float2 p1 = __half22float2(*(__half2*)&u.y);
            acc.x = fmaf(p0.x, w, acc.x); acc.y = fmaf(p0.y, w, acc.y);
            acc.z = fmaf(p1.x, w, acc.z); acc.w = fmaf(p1.y, w, acc.w);
        }
        float inv = 1.f / (d + 1e-16f);
        float4 b = *(const float4*)&bias0[coff];
        float4 o;
        o.x = acc.x * inv + b.x; o.y = acc.y * inv + b.y;
        o.z = acc.z * inv + b.z; o.w = acc.w * inv + b.w;
        *(float4*)&g_agg0[(size_t)n * 128 + coff] = o;

        atomicAdd(&s_sum[coff + 0], o.x); atomicAdd(&s_sq[coff + 0], o.x * o.x);
        atomicAdd(&s_sum[coff + 1], o.y); atomicAdd(&s_sq[coff + 1], o.y * o.y);
        atomicAdd(&s_sum[coff + 2], o.z); atomicAdd(&s_sq[coff + 2], o.z * o.z);
        atomicAdd(&s_sum[coff + 3], o.w); atomicAdd(&s_sq[coff + 3], o.w * o.w);
    }
    __syncthreads();
    if (tid < C0) {
        atomicAdd(&g_bnsum[tid], s_sum[tid]);
        atomicAdd(&g_bnsq[tid], s_sq[tid]);
    }
}

__global__ __launch_bounds__(256) void k_agg1(const float* __restrict__ bias1,
                                              float* __restrict__ out) {
    int n = (blockIdx.x * blockDim.x + threadIdx.x) >> 5;
    int lane = threadIdx.x & 31;
    if (n >= NN) return;
    int beg = g_off[n], end = g_off[n + 1];
    float ad = g_a1d[n];
    float an = g_a1s[n];
    int coff = lane * 2;

    float d = 0.f;
    float2 acc = make_float2(0.f, 0.f);
#pragma unroll 2
    for (int i = beg; i < end; i++) {
        int s = g_csr[i];
        float w = __expf(lrelu(g_a1s[s] + ad));
        d += w;
        unsigned u = *(const unsigned*)&g_h1h[(size_t)s * 64 + coff];
        float2 p = __half22float2(*(__half2*)&u);
        acc.x = fmaf(p.x, w, acc.x);
        acc.y = fmaf(p.y, w, acc.y);
    }
    { // self loop
        float w = __expf(lrelu(an + ad));
        d += w;
        unsigned u = *(const unsigned*)&g_h1h[(size_t)n * 64 + coff];
        float2 p = __half22float2(*(__half2*)&u);
        acc.x = fmaf(p.x, w, acc.x);
        acc.y = fmaf(p.y, w, acc.y);
    }
    float inv = 1.f / (d + 1e-16f);
    float2 b = *(const float2*)&bias1[coff];
    float2 r = make_float2(acc.x * inv + b.x, acc.y * inv + b.y);
    *(float2*)&out[(size_t)n * 64 + coff] = r;
}

// ---------------- launch ----------------------------------------------------
extern "C" void kernel_launch(void* const* d_in, const int* in_sizes, int n_in,
                              void* d_out, int out_size) {
    const float* data = (const float*)d_in[0];
    const int*   ei   = (const int*)d_in[1];    // int32 (JAX x64 disabled)
    const float* W0   = (const float*)d_in[2];
    const float* as0  = (const float*)d_in[3];
    const float* ad0  = (const float*)d_in[4];
    const float* b0   = (const float*)d_in[5];
    const float* g0   = (const float*)d_in[6];
    const float* be0  = (const float*)d_in[7];
    const float* W1   = (const float*)d_in[8];
    const float* as1  = (const float*)d_in[9];
    const float* ad1  = (const float*)d_in[10];
    const float* b1   = (const float*)d_in[11];
    float* out = (float*)d_out;

    int E = in_sizes[1] / 2;
    if (E > EMAX) E = EMAX;

    int warpBlocks = (NN * 32 + 255) / 256;

    static cudaStream_t s2 = nullptr;
    static cudaEvent_t evFork = nullptr, evJoin = nullptr;
    if (!s2) {
        cudaStreamCreateWithFlags(&s2, cudaStreamNonBlocking);
        cudaEventCreateWithFlags(&evFork, cudaEventDisableTiming);
        cudaEventCreateWithFlags(&evJoin, cudaEventDisableTiming);
    }

    // fork: CSR chain on s2
    cudaEventRecord(evFork, 0);
    cudaStreamWaitEvent(s2, evFork, 0);
    k_zero<<<(NN + 255) / 256, 256, 0, s2>>>();
    k_count<<<(E + 255) / 256, 256, 0, s2>>>(ei, E);
    k_scan<<<1, 1024, 0, s2>>>();
    k_scatter<<<(E + 255) / 256, 256, 0, s2>>>(ei, E);
    cudaEventRecord(evJoin, s2);

    // main stream: GEMM0 (tensor cores, 128x128 blocks) — independent of CSR
    k_gemm_tc<4, 2, false><<<(NN + 127) / 128, 256>>>(data, W0, as0, ad0, nullptr, nullptr, NN);

    // join, then dependent chain
    cudaStreamWaitEvent(0, evJoin, 0);
    k_agg0<<<warpBlocks, 256>>>(b0);
    k_gemm_tc<8, 1, true><<<(NN + 255) / 256, 256>>>(nullptr, W1, as1, ad1, g0, be0, NN);
    k_agg1<<<warpBlocks, 256>>>(b1, out);
}

// round 9
// speedup vs baseline: 1.0860x; 1.0349x over previous
#include <cuda_runtime.h>
#include <cuda_fp16.h>
#include <math.h>

#define NN   50000
#define C0   128      // HEADS*HID
#define OUTC 64
#define EMAX 800000
#define NEG  0.2f

// ---------------- scratch (static device globals; no allocation) ------------
__device__ __align__(16) int    g_deg[NN];
__device__ __align__(16) int    g_off[NN + 4];
__device__ __align__(16) int    g_cur[NN];
__device__ __align__(16) int    g_csr[EMAX];
__device__ __align__(16) __half g_h0h[(size_t)NN * C0];
__device__ __align__(16) __half g_h1h[(size_t)NN * OUTC];
__device__ __align__(16) float  g_as0[NN * 2];
__device__ __align__(16) float  g_ad0[NN * 2];
__device__ __align__(16) float  g_agg0[(size_t)NN * C0];
__device__ __align__(16) float  g_bnsum[C0];
__device__ __align__(16) float  g_bnsq[C0];
__device__ __align__(16) float  g_a1s[NN];
__device__ __align__(16) float  g_a1d[NN];

// ---------------- CSR build -------------------------------------------------
__global__ void k_zero() {
    int i = blockIdx.x * blockDim.x + threadIdx.x;
    if (i < NN) g_deg[i] = 0;
    if (i < C0) { g_bnsum[i] = 0.f; g_bnsq[i] = 0.f; }
}

__global__ void k_count(const int* __restrict__ ei, int E) {
    int i = blockIdx.x * blockDim.x + threadIdx.x;
    if (i < E) {
        int d = ei[E + i];
        if (d >= 0 && d < NN) atomicAdd(&g_deg[d], 1);
    }
}

__global__ void k_scan() {
    __shared__ int part[1024];
    int t = threadIdx.x;
    const int chunk = (NN + 1023) / 1024;
    int beg = t * chunk;
    int end = min(beg + chunk, NN);
    int s = 0;
    for (int i = beg; i < end; i++) s += g_deg[i];
    part[t] = s;
    __syncthreads();
    for (int d = 1; d < 1024; d <<= 1) {
        int v = 0;
        if (t >= d) v = part[t - d];
        __syncthreads();
        part[t] += v;
        __syncthreads();
    }
    int base = (t == 0) ? 0 : part[t - 1];
    for (int i = beg; i < end; i++) {
        g_off[i] = base; g_cur[i] = base; base += g_deg[i];
    }
    if (t == 1023) g_off[NN] = part[1023];
}

__global__ void k_scatter(const int* __restrict__ ei, int E) {
    int i = blockIdx.x * blockDim.x + threadIdx.x;
    if (i < E) {
        int d = ei[E + i];
        int s = ei[i];
        if (d >= 0 && d < NN && s >= 0 && s < NN) {
            int p = atomicAdd(&g_cur[d], 1);
            g_csr[p] = s;
        }
    }
}

// ---------------- SGEMM (K = 128 fixed) + fused epilogue (R5 proven) --------
// 128 rows per block, 256 threads.
template <int BNCOLS, bool TRANS>
__global__ __launch_bounds__(256) void k_gemm(const float* __restrict__ Ax,
                                              const float* __restrict__ W,
                                              const float* __restrict__ att_s,
                                              const float* __restrict__ att_d,
                                              const float* __restrict__ gamma,
                                              const float* __restrict__ beta,
                                              int nrows) {
    const int TN = BNCOLS / 16;          // 8 or 4
    __shared__ float As[8][128];
    __shared__ float Bs[8][BNCOLS];
    __shared__ float sSc[128], sSh[128];
    const float* A = TRANS ? g_agg0 : Ax;

    int tid = threadIdx.x;
    int row0 = blockIdx.x * 128;
    int ty = tid / 16, tx = tid % 16;

    if (TRANS) {
        if (tid < 128) {
            float mu = g_bnsum[tid] / (float)NN;
            float var = g_bnsq[tid] / (float)NN - mu * mu;
            float sc = gamma[tid] * rsqrtf(var + 1e-5f);
            sSc[tid] = sc;
            sSh[tid] = beta[tid] - mu * sc;
        }
        __syncthreads();
    }

    float acc[8][TN];
#pragma unroll
    for (int i = 0; i < 8; i++)
#pragma unroll
        for (int j = 0; j < TN; j++) acc[i][j] = 0.f;

    for (int kk = 0; kk < 128; kk += 8) {
        {
            int ar = tid >> 1;
            int ak = (tid & 1) * 4;
            int grow = row0 + ar;
            float4 v = make_float4(0.f, 0.f, 0.f, 0.f);
            if (grow < nrows)
                v = *(const float4*)&A[(size_t)grow * 128 + kk + ak];
            if (TRANS) {
                int c = kk + ak;
                float t0 = v.x * sSc[c] + sSh[c];
                float t1 = v.y * sSc[c + 1] + sSh[c + 1];
                float t2 = v.z * sSc[c + 2] + sSh[c + 2];
                float t3 = v.w * sSc[c + 3] + sSh[c + 3];
                v.x = t0 > 0.f ? t0 : expm1f(t0);
                v.y = t1 > 0.f ? t1 : expm1f(t1);
                v.z = t2 > 0.f ? t2 : expm1f(t2);
                v.w = t3 > 0.f ? t3 : expm1f(t3);
            }
            As[ak + 0][ar] = v.x; As[ak + 1][ar] = v.y;
            As[ak + 2][ar] = v.z; As[ak + 3][ar] = v.w;
        }
        if (BNCOLS == 128) {
            int bk = tid >> 5, bc = (tid & 31) * 4;
            float4 v = *(const float4*)&W[(size_t)(kk + bk) * BNCOLS + bc];
            *(float4*)&Bs[bk][bc] = v;
        } else {
            int bk = tid >> 5, bc = (tid & 31) * 2;
            float2 v = *(const float2*)&W[(size_t)(kk + bk) * BNCOLS + bc];
            Bs[bk][bc] = v.x; Bs[bk][bc + 1] = v.y;
        }
        __syncthreads();
#pragma unroll
        for (int k = 0; k < 8; k++) {
            float ra[8], rb[TN];
#pragma unroll
            for (int i = 0; i < 8; i++) ra[i] = As[k][ty * 8 + i];
#pragma unroll
            for (int j = 0; j < TN; j++) rb[j] = Bs[k][tx * TN + j];
#pragma unroll
            for (int i = 0; i < 8; i++)
#pragma unroll
                for (int j = 0; j < TN; j++) acc[i][j] = fmaf(ra[i], rb[j], acc[i][j]);
        }
        __syncthreads();
    }

    float vs[TN], vd[TN];
#pragma unroll
    for (int j = 0; j < TN; j++) {
        vs[j] = att_s[tx * TN + j];
        vd[j] = att_d[tx * TN + j];
    }

#pragma unroll
    for (int i = 0; i < 8; i++) {
        int r = row0 + ty * 8 + i;
        bool ok = (r < nrows);
        if (ok) {   // fp16 feature store
            if (BNCOLS == 128) {
                __half2 hp[4];
#pragma unroll
                for (int j = 0; j < 4; j++)
                    hp[j] = __floats2half2_rn(acc[i][2 * j], acc[i][2 * j + 1]);
                *(uint4*)&g_h0h[(size_t)r * 128 + tx * 8] = *(uint4*)hp;
            } else {
                __half2 hp[2];
                hp[0] = __floats2half2_rn(acc[i][0], acc[i][1]);
                hp[1] = __floats2half2_rn(acc[i][2], acc[i][3]);
                *(uint2*)&g_h1h[(size_t)r * 64 + tx * 4] = *(uint2*)hp;
            }
        }
        float ps = 0.f, pd = 0.f;
#pragma unroll
        for (int j = 0; j < TN; j++) {
            ps = fmaf(acc[i][j], vs[j], ps);
            pd = fmaf(acc[i][j], vd[j], pd);
        }
        if (BNCOLS == 128) {
#pragma unroll
            for (int o = 4; o; o >>= 1) {
                ps += __shfl_down_sync(0xffffffffu, ps, o, 8);
                pd += __shfl_down_sync(0xffffffffu, pd, o, 8);
            }
            if (ok && (tx & 7) == 0) {
                g_as0[r * 2 + (tx >> 3)] = ps;
                g_ad0[r * 2 + (tx >> 3)] = pd;
            }
        } else {
#pragma unroll
            for (int o = 8; o; o >>= 1) {
                ps += __shfl_down_sync(0xffffffffu, ps, o, 16);
                pd += __shfl_down_sync(0xffffffffu, pd, o, 16);
            }
            if (ok && tx == 0) {
                g_a1s[r] = ps;
                g_a1d[r] = pd;
            }
        }
    }
}

// ---------------- softmax-aggregate, MLP-friendly (warp per node) -----------
// Phase A: 32 lanes compute (src, weight) for 32 edges in parallel.
// Phase B: shfl-broadcast each edge; feature gathers are independent -> deep MLP.
__device__ __forceinline__ float lrelu(float x) { return x > 0.f ? x : NEG * x; }

__global__ __launch_bounds__(256) void k_agg0(const float* __restrict__ bias0) {
    __shared__ float s_sum[C0];
    __shared__ float s_sq[C0];
    int tid = threadIdx.x;
    if (tid < C0) { s_sum[tid] = 0.f; s_sq[tid] = 0.f; }
    __syncthreads();

    int n = (blockIdx.x * blockDim.x + tid) >> 5;
    int lane = tid & 31;
    if (n < NN) {
        int beg = g_off[n], end = g_off[n + 1];
        float2 ad = *(const float2*)&g_ad0[n * 2];
        float2 an = *(const float2*)&g_as0[n * 2];
        bool head1 = lane >= 16;
        int coff = lane * 4;

        float dsum0 = 0.f, dsum1 = 0.f;
        float4 acc = make_float4(0.f, 0.f, 0.f, 0.f);

        for (int base = beg; base < end; base += 32) {
            int i = base + lane;
            int cnt = min(32, end - base);
            int s = 0;
            float w0 = 0.f, w1 = 0.f;
            if (i < end) {
                s = g_csr[i];
                float2 a = *(const float2*)&g_as0[s * 2];
                w0 = __expf(lrelu(a.x + ad.x));
                w1 = __expf(lrelu(a.y + ad.y));
            }
            dsum0 += w0;
            dsum1 += w1;
#pragma unroll 4
            for (int j = 0; j < cnt; j++) {
                int sj = __shfl_sync(0xffffffffu, s, j);
                float wj0 = __shfl_sync(0xffffffffu, w0, j);
                float wj1 = __shfl_sync(0xffffffffu, w1, j);
                float wj = head1 ? wj1 : wj0;
                uint2 u = *(const uint2*)&g_h0h[(size_t)sj * 128 + coff];
                float2 p0 = __half22float2(*(__half2*)&u.x);
                float2 p1 = __half22float2(*(__half2*)&u.y);
                acc.x = fmaf(p0.x, wj, acc.x); acc.y = fmaf(p0.y, wj, acc.y);
                acc.z = fmaf(p1.x, wj, acc.z); acc.w = fmaf(p1.y, wj, acc.w);
            }
        }
#pragma unroll
        for (int o = 16; o; o >>= 1) {
            dsum0 += __shfl_xor_sync(0xffffffffu, dsum0, o);
            dsum1 += __shfl_xor_sync(0xffffffffu, dsum1, o);
        }
        // self loop
        float ws0 = __expf(lrelu(an.x + ad.x));
        float ws1 = __expf(lrelu(an.y + ad.y));
        dsum0 += ws0; dsum1 += ws1;
        {
            float wsh = head1 ? ws1 : ws0;
            uint2 u = *(const uint2*)&g_h0h[(size_t)n * 128 + coff];
            float2 p0 = __half22float2(*(__half2*)&u.x);
            float2 p1 = __half22float2(*(__half2*)&u.y);
            acc.x = fmaf(p0.x, wsh, acc.x); acc.y = fmaf(p0.y, wsh, acc.y);
            acc.z = fmaf(p1.x, wsh, acc.z); acc.w = fmaf(p1.y, wsh, acc.w);
        }
        float inv = 1.f / ((head1 ? dsum1 : dsum0) + 1e-16f);
        float4 b = *(const float4*)&bias0[coff];
        float4 o;
        o.x = acc.x * inv + b.x; o.y = acc.y * inv + b.y;
        o.z = acc.z * inv + b.z; o.w = acc.w * inv + b.w;
        *(float4*)&g_agg0[(size_t)n * 128 + coff] = o;

        atomicAdd(&s_sum[coff + 0], o.x); atomicAdd(&s_sq[coff + 0], o.x * o.x);
        atomicAdd(&s_sum[coff + 1], o.y); atomicAdd(&s_sq[coff + 1], o.y * o.y);
        atomicAdd(&s_sum[coff + 2], o.z); atomicAdd(&s_sq[coff + 2], o.z * o.z);
        atomicAdd(&s_sum[coff + 3], o.w); atomicAdd(&s_sq[coff + 3], o.w * o.w);
    }
    __syncthreads();
    if (tid < C0) {
        atomicAdd(&g_bnsum[tid], s_sum[tid]);
        atomicAdd(&g_bnsq[tid], s_sq[tid]);
    }
}

__global__ __launch_bounds__(256) void k_agg1(const float* __restrict__ bias1,
                                              float* __restrict__ out) {
    int n = (blockIdx.x * blockDim.x + threadIdx.x) >> 5;
    int lane = threadIdx.x & 31;
    if (n >= NN) return;
    int beg = g_off[n], end = g_off[n + 1];
    float ad = g_a1d[n];
    float an = g_a1s[n];
    int coff = lane * 2;

    float dsum = 0.f;
    float2 acc = make_float2(0.f, 0.f);
    for (int base = beg; base < end; base += 32) {
        int i = base + lane;
        int cnt = min(32, end - base);
        int s = 0;
        float w = 0.f;
        if (i < end) {
            s = g_csr[i];
            w = __expf(lrelu(g_a1s[s] + ad));
        }
        dsum += w;
#pragma unroll 4
        for (int j = 0; j < cnt; j++) {
            int sj = __shfl_sync(0xffffffffu, s, j);
            float wj = __shfl_sync(0xffffffffu, w, j);
            unsigned u = *(const unsigned*)&g_h1h[(size_t)sj * 64 + coff];
            float2 p = __half22float2(*(__half2*)&u);
            acc.x = fmaf(p.x, wj, acc.x);
            acc.y = fmaf(p.y, wj, acc.y);
        }
    }
#pragma unroll
    for (int o = 16; o; o >>= 1)
        dsum += __shfl_xor_sync(0xffffffffu, dsum, o);
    // self loop
    float ws = __expf(lrelu(an + ad));
    dsum += ws;
    {
        unsigned u = *(const unsigned*)&g_h1h[(size_t)n * 64 + coff];
        float2 p = __half22float2(*(__half2*)&u);
        acc.x = fmaf(p.x, ws, acc.x);
        acc.y = fmaf(p.y, ws, acc.y);
    }
    float inv = 1.f / (dsum + 1e-16f);
    float2 b = *(const float2*)&bias1[coff];
    float2 r = make_float2(acc.x * inv + b.x, acc.y * inv + b.y);
    *(float2*)&out[(size_t)n * 64 + coff] = r;
}

// ---------------- launch ----------------------------------------------------
extern "C" void kernel_launch(void* const* d_in, const int* in_sizes, int n_in,
                              void* d_out, int out_size) {
    const float* data = (const float*)d_in[0];
    const int*   ei   = (const int*)d_in[1];    // int32 (JAX x64 disabled)
    const float* W0   = (const float*)d_in[2];
    const float* as0  = (const float*)d_in[3];
    const float* ad0  = (const float*)d_in[4];
    const float* b0   = (const float*)d_in[5];
    const float* g0   = (const float*)d_in[6];
    const float* be0  = (const float*)d_in[7];
    const float* W1   = (const float*)d_in[8];
    const float* as1  = (const float*)d_in[9];
    const float* ad1  = (const float*)d_in[10];
    const float* b1   = (const float*)d_in[11];
    float* out = (float*)d_out;

    int E = in_sizes[1] / 2;
    if (E > EMAX) E = EMAX;

    int warpBlocks = (NN * 32 + 255) / 256;

    static cudaStream_t s2 = nullptr;
    static cudaEvent_t evFork = nullptr, evJoin = nullptr;
    if (!s2) {
        cudaStreamCreateWithFlags(&s2, cudaStreamNonBlocking);
        cudaEventCreateWithFlags(&evFork, cudaEventDisableTiming);
        cudaEventCreateWithFlags(&evJoin, cudaEventDisableTiming);
    }

    // fork: CSR chain on s2
    cudaEventRecord(evFork, 0);
    cudaStreamWaitEvent(s2, evFork, 0);
    k_zero<<<(NN + 255) / 256, 256, 0, s2>>>();
    k_count<<<(E + 255) / 256, 256, 0, s2>>>(ei, E);
    k_scan<<<1, 1024, 0, s2>>>();
    k_scatter<<<(E + 255) / 256, 256, 0, s2>>>(ei, E);
    cudaEventRecord(evJoin, s2);

    // main stream: GEMM0 (independent of CSR)
    k_gemm<128, false><<<(NN + 127) / 128, 256>>>(data, W0, as0, ad0, nullptr, nullptr, NN);

    // join, then dependent chain
    cudaStreamWaitEvent(0, evJoin, 0);
    k_agg0<<<warpBlocks, 256>>>(b0);
    k_gemm<64, true><<<(NN + 127) / 128, 256>>>(nullptr, W1, as1, ad1, g0, be0, NN);
    k_agg1<<<warpBlocks, 256>>>(b1, out);
}